// round 16
// baseline (speedup 1.0000x reference)
#include <cuda_runtime.h>
#include <cstdint>

#define THREADS 256

// 256-bit gather with L2 evict_last (sm_103 requires .v8.b32 for evict_last).
// volatile: pins issue order so ptxas cannot interleave consumers between the
// 7 gathers (R14 compiled to 38 regs => MLP collapsed to ~3; we want 7-deep).
__device__ __forceinline__ void ld256_el(const float* p, float* d) {
    uint32_t a, b, c, e, f, g, h, i;
    asm volatile(
        "ld.global.nc.L2::evict_last.v8.b32 {%0,%1,%2,%3,%4,%5,%6,%7}, [%8];"
        : "=r"(a), "=r"(b), "=r"(c), "=r"(e),
          "=r"(f), "=r"(g), "=r"(h), "=r"(i) : "l"(p));
    d[0] = __uint_as_float(a); d[1] = __uint_as_float(b);
    d[2] = __uint_as_float(c); d[3] = __uint_as_float(e);
    d[4] = __uint_as_float(f); d[5] = __uint_as_float(g);
    d[6] = __uint_as_float(h); d[7] = __uint_as_float(i);
}

// One warp = two triples; each half-warp (16 lanes) owns one triple.
// Lane l loads floats [8*(l%16), 8*(l%16)+8) of each of 7 rows (LDG.256).
// bases rows are L2-normalized (v.v == 1); projector linear with shared v:
//   sum|P(h)+P(r)-P(t)| = sum|P(h+r-t)|,  c = v.(h+r-t).
__global__ __launch_bounds__(THREADS, 4)   // allow up to 64 regs/thread
void transh_score_v8d_kernel(
    const int* __restrict__ pos_h, const int* __restrict__ pos_t, const int* __restrict__ pos_r,
    const int* __restrict__ neg_h, const int* __restrict__ neg_t, const int* __restrict__ neg_r,
    const float* __restrict__ ent,    // [ENT, 128]
    const float* __restrict__ vvrel,  // [ENT, 128]
    const float* __restrict__ bases,  // [REL, 128]
    float* __restrict__ out, int n)
{
    const int warp = (blockIdx.x * blockDim.x + threadIdx.x) >> 5;
    const int lane = threadIdx.x & 31;
    const int grp  = lane >> 4;          // 0: triple 2w, 1: triple 2w+1
    const int hl   = lane & 15;          // lane within half-warp
    const int iA   = 2 * warp;
    if (iA >= n) return;
    const int iB   = iA + 1;
    const bool hasB = (iB < n);
    const int  i    = grp ? (hasB ? iB : iA) : iA;   // this half-warp's triple

    const int ih = __ldg(pos_h + i);
    const int it = __ldg(pos_t + i);
    const int ir = __ldg(pos_r + i);
    const int jh = __ldg(neg_h + i);
    const int jt = __ldg(neg_t + i);
    const int jr = __ldg(neg_r + i);

    const int off = hl * 8;   // float offset within the 128-float row

    // 7 independent 32B gathers per thread, forced back-to-back.
    float v[8], h[8], t[8], r[8], nh[8], nt[8], nr[8];
    ld256_el(bases + (size_t)ir * 128 + off, v);
    ld256_el(ent   + (size_t)ih * 128 + off, h);
    ld256_el(ent   + (size_t)it * 128 + off, t);
    ld256_el(vvrel + (size_t)ir * 128 + off, r);
    ld256_el(ent   + (size_t)jh * 128 + off, nh);
    ld256_el(ent   + (size_t)jt * 128 + off, nt);
    ld256_el(vvrel + (size_t)jr * 128 + off, nr);

    float dp[8], dn[8];
    #pragma unroll
    for (int k = 0; k < 8; ++k) {
        dp[k] = h[k]  + r[k]  - t[k];
        dn[k] = nh[k] + nr[k] - nt[k];
    }

    // Stage 1: dots v.dp, v.dn over this half-warp (16 lanes x 8 floats).
    float cp = 0.f, cn = 0.f;
    #pragma unroll
    for (int k = 0; k < 8; ++k) {
        cp = fmaf(v[k], dp[k], cp);
        cn = fmaf(v[k], dn[k], cn);
    }
    #pragma unroll
    for (int o = 8; o > 0; o >>= 1) {        // stays within the half-warp
        cp += __shfl_xor_sync(0xFFFFFFFFu, cp, o);
        cn += __shfl_xor_sync(0xFFFFFFFFu, cn, o);
    }

    // Stage 2: L1 norms of projected differences (v.v == 1 -> c = v.d).
    float sp = 0.f, sn = 0.f;
    #pragma unroll
    for (int k = 0; k < 8; ++k) {
        sp += fabsf(dp[k] - cp * v[k]);
        sn += fabsf(dn[k] - cn * v[k]);
    }
    #pragma unroll
    for (int o = 8; o > 0; o >>= 1) {
        sp += __shfl_xor_sync(0xFFFFFFFFu, sp, o);
        sn += __shfl_xor_sync(0xFFFFFFFFu, sn, o);
    }

    if (hl == 0 && (grp == 0 || hasB)) {
        out[i]     = sp;
        out[n + i] = sn;
    }
}

extern "C" void kernel_launch(void* const* d_in, const int* in_sizes, int n_in,
                              void* d_out, int out_size)
{
    const int*   pos_h = (const int*)d_in[0];
    const int*   pos_t = (const int*)d_in[1];
    const int*   pos_r = (const int*)d_in[2];
    const int*   neg_h = (const int*)d_in[3];
    const int*   neg_t = (const int*)d_in[4];
    const int*   neg_r = (const int*)d_in[5];
    const float* ent   = (const float*)d_in[6];
    const float* vvrel = (const float*)d_in[7];
    const float* bases = (const float*)d_in[8];
    float* out = (float*)d_out;

    const int n = in_sizes[0];  // 65536 triples
    const int nwarps = (n + 1) / 2;
    const int warps_per_block = THREADS / 32;
    const int blocks = (nwarps + warps_per_block - 1) / warps_per_block;
    transh_score_v8d_kernel<<<blocks, THREADS>>>(
        pos_h, pos_t, pos_r, neg_h, neg_t, neg_r, ent, vvrel, bases, out, n);
}